// round 2
// baseline (speedup 1.0000x reference)
#include <cuda_runtime.h>
#include <math.h>
#include <float.h>

// Problem constants
#define NS 25      // support count (WAY*SHOT)
#define NQ 75      // query count (WAY*QUERY_SHOT)
#define DD 640     // feature dim
#define MM 25      // M (inner dim)

// Scratch: P[q][s][d] = sum_m S[s,d,m]*W[s,q,m]  (unnormalized)
__device__ float g_P[NQ * NS * DD];

// ---------------------------------------------------------------------------
// Kernel 1: per-s GEMM. P[q][s][d] = sum_m W[s,q,m] * S[s,d,m]
// grid = (5 d-chunks of 128, 25 s), block = 256 (8 warps).
// Each warp: 10 q rows x 4 d (float4 per lane). acc[10][4].
// ---------------------------------------------------------------------------
__global__ __launch_bounds__(256) void k1_proj_support(
        const float* __restrict__ fm, const float* __restrict__ w2) {
    const int s  = blockIdx.y;
    const int d0 = blockIdx.x * 128;

    __shared__ __align__(16) float Wsm[MM][80];   // [m][q], q padded to 80
    __shared__ __align__(16) float Ssm[MM][132];  // [m][d], 128 d (+pad)

    const int tid = threadIdx.x;

    // Stage W[s,:,:] -> Wsm[m][q]   (coalesced global reads)
    for (int idx = tid; idx < NQ * MM; idx += 256) {
        int q = idx / MM, m = idx - q * MM;
        Wsm[m][q] = w2[s * (NQ * MM) + idx];
    }
    for (int idx = tid; idx < 5 * MM; idx += 256) {       // zero-pad q=75..79
        int m = idx % MM, q = NQ + idx / MM;
        Wsm[m][q] = 0.0f;
    }
    // Stage S[s, d0:d0+128, :] -> Ssm[m][d]
    for (int idx = tid; idx < 128 * MM; idx += 256) {
        int d = idx / MM, m = idx - d * MM;
        Ssm[m][d] = fm[s * (DD * MM) + d0 * MM + idx];
    }
    __syncthreads();

    const int lane = tid & 31;
    const int qb   = (tid >> 5) * 10;   // warp -> q base (0..70)

    float acc[10][4];
#pragma unroll
    for (int j = 0; j < 10; j++)
#pragma unroll
        for (int i = 0; i < 4; i++) acc[j][i] = 0.0f;

#pragma unroll
    for (int m = 0; m < MM; m++) {
        float4 bv = *reinterpret_cast<const float4*>(&Ssm[m][lane * 4]);
#pragma unroll
        for (int j = 0; j < 10; j++) {
            float a = Wsm[m][qb + j];
            acc[j][0] = fmaf(a, bv.x, acc[j][0]);
            acc[j][1] = fmaf(a, bv.y, acc[j][1]);
            acc[j][2] = fmaf(a, bv.z, acc[j][2]);
            acc[j][3] = fmaf(a, bv.w, acc[j][3]);
        }
    }

#pragma unroll
    for (int j = 0; j < 10; j++) {
        int q = qb + j;
        if (q < NQ) {
            float4 v = make_float4(acc[j][0], acc[j][1], acc[j][2], acc[j][3]);
            *reinterpret_cast<float4*>(&g_P[(q * NS + s) * DD + d0 + lane * 4]) = v;
        }
    }
}

// ---------------------------------------------------------------------------
// Kernel 2 (fused): per-q GEMM + L2 accumulation + log-softmax.
// grid = 75 (one block per q), block = 256 (8 warps).
// Each warp owns 4 s rows; lanes own 4 d each; loop over 5 d-chunks of 128.
// l2 partials stay in registers across chunks; one shuffle-reduce at the end;
// warp 0 does the 25-wide softmax inline. No global atomics, no 3rd kernel.
// ---------------------------------------------------------------------------
__global__ __launch_bounds__(256) void k2_query_softmax(
        const float* __restrict__ fm, const float* __restrict__ w2,
        const float* __restrict__ scale, float* __restrict__ out) {
    const int q = blockIdx.x;

    __shared__ __align__(16) float Wsm[MM][36];   // [m][s], s padded to 32(+4)
    __shared__ __align__(16) float Qsm[MM][132];  // [m][d], 128 d (+pad)
    __shared__ float l2row[32];

    const int tid = threadIdx.x;

    // Stage W[:,q,:] -> Wsm[m][s], zero-pad s=25..31
    for (int idx = tid; idx < NS * MM; idx += 256) {
        int sI = idx / MM, m = idx - sI * MM;
        Wsm[m][sI] = w2[(sI * NQ + q) * MM + m];
    }
    for (int idx = tid; idx < 7 * MM; idx += 256) {
        int m = idx % MM, sI = NS + idx / MM;
        Wsm[m][sI] = 0.0f;
    }

    const int lane = tid & 31;
    const int sb   = (tid >> 5) * 4;   // warp -> s base (0..28)

    float l2acc[4] = {0.0f, 0.0f, 0.0f, 0.0f};

    for (int chunk = 0; chunk < 5; chunk++) {
        const int d0 = chunk * 128;
        __syncthreads();
        for (int idx = tid; idx < 128 * MM; idx += 256) {
            int d = idx / MM, m = idx - d * MM;
            Qsm[m][d] = fm[(NS + q) * (DD * MM) + d0 * MM + idx];
        }
        __syncthreads();

        float acc[4][4];
#pragma unroll
        for (int j = 0; j < 4; j++)
#pragma unroll
            for (int i = 0; i < 4; i++) acc[j][i] = 0.0f;

#pragma unroll
        for (int m = 0; m < MM; m++) {
            float4 bv = *reinterpret_cast<const float4*>(&Qsm[m][lane * 4]);
            float4 av = *reinterpret_cast<const float4*>(&Wsm[m][sb]);
            acc[0][0] = fmaf(av.x, bv.x, acc[0][0]);
            acc[0][1] = fmaf(av.x, bv.y, acc[0][1]);
            acc[0][2] = fmaf(av.x, bv.z, acc[0][2]);
            acc[0][3] = fmaf(av.x, bv.w, acc[0][3]);
            acc[1][0] = fmaf(av.y, bv.x, acc[1][0]);
            acc[1][1] = fmaf(av.y, bv.y, acc[1][1]);
            acc[1][2] = fmaf(av.y, bv.z, acc[1][2]);
            acc[1][3] = fmaf(av.y, bv.w, acc[1][3]);
            acc[2][0] = fmaf(av.z, bv.x, acc[2][0]);
            acc[2][1] = fmaf(av.z, bv.y, acc[2][1]);
            acc[2][2] = fmaf(av.z, bv.z, acc[2][2]);
            acc[2][3] = fmaf(av.z, bv.w, acc[2][3]);
            acc[3][0] = fmaf(av.w, bv.x, acc[3][0]);
            acc[3][1] = fmaf(av.w, bv.y, acc[3][1]);
            acc[3][2] = fmaf(av.w, bv.z, acc[3][2]);
            acc[3][3] = fmaf(av.w, bv.w, acc[3][3]);
        }

#pragma unroll
        for (int j = 0; j < 4; j++) {
            int s = sb + j;
            if (s < NS) {
                float4 pv = *reinterpret_cast<const float4*>(
                    &g_P[(q * NS + s) * DD + d0 + lane * 4]);
                float t0 = acc[j][0] - pv.x;
                float t1 = acc[j][1] - pv.y;
                float t2 = acc[j][2] - pv.z;
                float t3 = acc[j][3] - pv.w;
                l2acc[j] += t0 * t0 + t1 * t1 + t2 * t2 + t3 * t3;
            }
        }
    }

    // One shuffle-reduce over lanes, per owned s row
#pragma unroll
    for (int j = 0; j < 4; j++) {
        float v = l2acc[j];
#pragma unroll
        for (int off = 16; off > 0; off >>= 1)
            v += __shfl_down_sync(0xffffffffu, v, off);
        int s = sb + j;
        if (lane == 0 && s < NS) l2row[s] = v;
    }
    __syncthreads();

    // Warp 0: scale + log-softmax over the 25 support classes
    if (tid < 32) {
        const float c = -scale[0] / 312500.0f;  // 1/(M^2 * G*Q*Q*SHOT)
        float logit = (tid < NS) ? l2row[tid] * c : -FLT_MAX;

        float mx = logit;
#pragma unroll
        for (int off = 16; off > 0; off >>= 1)
            mx = fmaxf(mx, __shfl_xor_sync(0xffffffffu, mx, off));

        float e = (tid < NS) ? expf(logit - mx) : 0.0f;
        float sum = e;
#pragma unroll
        for (int off = 16; off > 0; off >>= 1)
            sum += __shfl_xor_sync(0xffffffffu, sum, off);

        if (tid < NS)
            out[q * NS + tid] = logit - mx - logf(sum);
    }
}

// ---------------------------------------------------------------------------
extern "C" void kernel_launch(void* const* d_in, const int* in_sizes, int n_in,
                              void* d_out, int out_size) {
    const float* fm    = (const float*)d_in[0];  // (100, 640, 25) f32
    const float* w2    = (const float*)d_in[1];  // (25, 75, 25) f32
    const float* scale = (const float*)d_in[2];  // (1,) f32
    float* out = (float*)d_out;                  // (75, 25) f32

    k1_proj_support<<<dim3(5, 25), 256>>>(fm, w2);
    k2_query_softmax<<<NQ, 256>>>(fm, w2, scale, out);
}

// round 3
// speedup vs baseline: 1.1099x; 1.1099x over previous
#include <cuda_runtime.h>
#include <math.h>
#include <float.h>

// Problem constants
#define NS 25      // support count (WAY*SHOT)
#define NQ 75      // query count (WAY*QUERY_SHOT)
#define DD 640     // feature dim
#define MM 25      // M (inner dim)

// Scratch (device globals)
__device__ float g_P[NQ * NS * DD];   // P[q][s][d] = sum_m S[s,d,m]*W[s,q,m]
__device__ float g_l2[NQ * NS];       // raw sum_d (p-r)^2, [q][s]
__device__ int   g_cnt[NQ];           // chunk completion tickets per q

// ---------------------------------------------------------------------------
// Kernel 1: per-s GEMM. P[q][s][d] = sum_m W[s,q,m] * S[s,d,m]
// grid = (5 d-chunks of 128, 25 s), block = 256 (8 warps).
// Each warp: 10 q rows x 4 d (float4 per lane).
// Block (0,0) also zeroes g_l2 and g_cnt for this replay.
// ---------------------------------------------------------------------------
__global__ __launch_bounds__(256) void k1_proj_support(
        const float* __restrict__ fm, const float* __restrict__ w2) {
    const int s  = blockIdx.y;
    const int d0 = blockIdx.x * 128;

    __shared__ __align__(16) float Wsm[MM][80];   // [m][q], q padded to 80
    __shared__ __align__(16) float Ssm[MM][132];  // [m][d], 128 d (+pad)

    const int tid = threadIdx.x;

    for (int idx = tid; idx < NQ * MM; idx += 256) {
        int q = idx / MM, m = idx - q * MM;
        Wsm[m][q] = w2[s * (NQ * MM) + idx];
    }
    for (int idx = tid; idx < 5 * MM; idx += 256) {       // zero-pad q=75..79
        int m = idx % MM, q = NQ + idx / MM;
        Wsm[m][q] = 0.0f;
    }
    for (int idx = tid; idx < 128 * MM; idx += 256) {
        int d = idx / MM, m = idx - d * MM;
        Ssm[m][d] = fm[s * (DD * MM) + d0 * MM + idx];
    }
    if (blockIdx.x == 0 && s == 0) {
        for (int i = tid; i < NQ * NS; i += 256) g_l2[i] = 0.0f;
        for (int i = tid; i < NQ; i += 256) g_cnt[i] = 0;
    }
    __syncthreads();

    const int lane = tid & 31;
    const int qb   = (tid >> 5) * 10;   // warp -> q base (0..70)

    float acc[10][4];
#pragma unroll
    for (int j = 0; j < 10; j++)
#pragma unroll
        for (int i = 0; i < 4; i++) acc[j][i] = 0.0f;

#pragma unroll
    for (int m = 0; m < MM; m++) {
        float4 bv = *reinterpret_cast<const float4*>(&Ssm[m][lane * 4]);
#pragma unroll
        for (int j = 0; j < 10; j++) {
            float a = Wsm[m][qb + j];
            acc[j][0] = fmaf(a, bv.x, acc[j][0]);
            acc[j][1] = fmaf(a, bv.y, acc[j][1]);
            acc[j][2] = fmaf(a, bv.z, acc[j][2]);
            acc[j][3] = fmaf(a, bv.w, acc[j][3]);
        }
    }

#pragma unroll
    for (int j = 0; j < 10; j++) {
        int q = qb + j;
        if (q < NQ) {
            float4 v = make_float4(acc[j][0], acc[j][1], acc[j][2], acc[j][3]);
            *reinterpret_cast<float4*>(&g_P[(q * NS + s) * DD + d0 + lane * 4]) = v;
        }
    }
}

// ---------------------------------------------------------------------------
// Kernel 2: per-(q, d-chunk) GEMM + fused L2 atomics + last-block softmax.
// grid = (5 d-chunks of 128, 75 q), block = 224 (7 warps).
// Each warp owns 4 s rows; lanes own 4 d. One chunk per block (no serial loop).
// After atomics, a per-q ticket decides which block runs the 25-wide softmax.
// ---------------------------------------------------------------------------
__global__ __launch_bounds__(224) void k2_query_acc_softmax(
        const float* __restrict__ fm, const float* __restrict__ w2,
        const float* __restrict__ scale, float* __restrict__ out) {
    const int q  = blockIdx.y;
    const int d0 = blockIdx.x * 128;

    __shared__ __align__(16) float Wsm[MM][36];   // [m][s], s padded to 32
    __shared__ __align__(16) float Qsm[MM][132];  // [m][d], 128 d (+pad)
    __shared__ int s_last;

    const int tid = threadIdx.x;  // 224

    for (int idx = tid; idx < NS * MM; idx += 224) {
        int sI = idx / MM, m = idx - sI * MM;
        Wsm[m][sI] = w2[(sI * NQ + q) * MM + m];
    }
    for (int idx = tid; idx < 7 * MM; idx += 224) {       // zero-pad s=25..31
        int m = idx % MM, sI = NS + idx / MM;
        Wsm[m][sI] = 0.0f;
    }
    for (int idx = tid; idx < 128 * MM; idx += 224) {
        int d = idx / MM, m = idx - d * MM;
        Qsm[m][d] = fm[(NS + q) * (DD * MM) + d0 * MM + idx];
    }
    __syncthreads();

    const int lane = tid & 31;
    const int sb   = (tid >> 5) * 4;   // warp -> s base (0..24)

    float acc[4][4];
#pragma unroll
    for (int j = 0; j < 4; j++)
#pragma unroll
        for (int i = 0; i < 4; i++) acc[j][i] = 0.0f;

#pragma unroll
    for (int m = 0; m < MM; m++) {
        float4 bv = *reinterpret_cast<const float4*>(&Qsm[m][lane * 4]);
        float4 av = *reinterpret_cast<const float4*>(&Wsm[m][sb]);
        acc[0][0] = fmaf(av.x, bv.x, acc[0][0]);
        acc[0][1] = fmaf(av.x, bv.y, acc[0][1]);
        acc[0][2] = fmaf(av.x, bv.z, acc[0][2]);
        acc[0][3] = fmaf(av.x, bv.w, acc[0][3]);
        acc[1][0] = fmaf(av.y, bv.x, acc[1][0]);
        acc[1][1] = fmaf(av.y, bv.y, acc[1][1]);
        acc[1][2] = fmaf(av.y, bv.z, acc[1][2]);
        acc[1][3] = fmaf(av.y, bv.w, acc[1][3]);
        acc[2][0] = fmaf(av.z, bv.x, acc[2][0]);
        acc[2][1] = fmaf(av.z, bv.y, acc[2][1]);
        acc[2][2] = fmaf(av.z, bv.z, acc[2][2]);
        acc[2][3] = fmaf(av.z, bv.w, acc[2][3]);
        acc[3][0] = fmaf(av.w, bv.x, acc[3][0]);
        acc[3][1] = fmaf(av.w, bv.y, acc[3][1]);
        acc[3][2] = fmaf(av.w, bv.z, acc[3][2]);
        acc[3][3] = fmaf(av.w, bv.w, acc[3][3]);
    }

    // Epilogue: (r - p)^2, reduce 4 local + 32 lanes, atomic add into g_l2.
#pragma unroll
    for (int j = 0; j < 4; j++) {
        int   s    = sb + j;
        float part = 0.0f;
        if (s < NS) {
            float4 pv = *reinterpret_cast<const float4*>(
                &g_P[(q * NS + s) * DD + d0 + lane * 4]);
            float t0 = acc[j][0] - pv.x;
            float t1 = acc[j][1] - pv.y;
            float t2 = acc[j][2] - pv.z;
            float t3 = acc[j][3] - pv.w;
            part = t0 * t0 + t1 * t1 + t2 * t2 + t3 * t3;
        }
#pragma unroll
        for (int off = 16; off > 0; off >>= 1)
            part += __shfl_down_sync(0xffffffffu, part, off);
        if (lane == 0 && s < NS)
            atomicAdd(&g_l2[q * NS + s], part);
    }

    // Ticket: last of the 5 chunk-blocks for this q runs the softmax.
    __syncthreads();
    __threadfence();
    if (tid == 0)
        s_last = (atomicAdd(&g_cnt[q], 1) == 4) ? 1 : 0;
    __syncthreads();

    if (s_last && tid < 32) {
        __threadfence();  // acquire: make other blocks' g_l2 adds visible
        const float c = -scale[0] / 312500.0f;  // 1/(M^2 * G*Q*Q*SHOT)
        float logit = (tid < NS) ? g_l2[q * NS + tid] * c : -FLT_MAX;

        float mx = logit;
#pragma unroll
        for (int off = 16; off > 0; off >>= 1)
            mx = fmaxf(mx, __shfl_xor_sync(0xffffffffu, mx, off));

        float e = (tid < NS) ? expf(logit - mx) : 0.0f;
        float sum = e;
#pragma unroll
        for (int off = 16; off > 0; off >>= 1)
            sum += __shfl_xor_sync(0xffffffffu, sum, off);

        if (tid < NS)
            out[q * NS + tid] = logit - mx - logf(sum);
    }
}

// ---------------------------------------------------------------------------
extern "C" void kernel_launch(void* const* d_in, const int* in_sizes, int n_in,
                              void* d_out, int out_size) {
    const float* fm    = (const float*)d_in[0];  // (100, 640, 25) f32
    const float* w2    = (const float*)d_in[1];  // (25, 75, 25) f32
    const float* scale = (const float*)d_in[2];  // (1,) f32
    float* out = (float*)d_out;                  // (75, 25) f32

    k1_proj_support<<<dim3(5, 25), 256>>>(fm, w2);
    k2_query_acc_softmax<<<dim3(5, NQ), 224>>>(fm, w2, scale, out);
}